// round 11
// baseline (speedup 1.0000x reference)
#include <cuda_runtime.h>
#include <math.h>
#include <stdint.h>

#define Bc 4
#define Tc 1024
#define Dc 1024
#define Hc 16
#define HSc 64
#define Lc 2047

__device__ float g_q[Bc * Tc * Dc];
__device__ float g_k[Bc * Tc * Dc];
__device__ float g_v[Bc * Tc * Dc];
__device__ float g_p[Lc * Dc];
__device__ float g_ctx[Bc * Tc * Dc];

__device__ __forceinline__ uint32_t tf32_of(float x) {
    uint32_t r;
    asm("cvt.rna.tf32.f32 %0, %1;" : "=r"(r) : "f"(x));
    return r;
}
__device__ __forceinline__ void mma_p(float* d, uint4 a, uint2 b) {
    asm volatile(
        "mma.sync.aligned.m16n8k8.row.col.f32.tf32.tf32.f32 "
        "{%0,%1,%2,%3},{%4,%5,%6,%7},{%8,%9},{%0,%1,%2,%3};"
        : "+f"(d[0]), "+f"(d[1]), "+f"(d[2]), "+f"(d[3])
        : "r"(a.x), "r"(a.y), "r"(a.z), "r"(a.w), "r"(b.x), "r"(b.y));
}

// FMA-pipe exp: 2^y via magic-round + degree-5 poly (no MUFU).
// valid for y in [-100, ~+30]; rel err ~2e-8.
__device__ __forceinline__ float fexp2(float y) {
    y = fmaxf(y, -100.f);
    float rn = y + 12582912.f;                       // 2^23+2^22 magic
    int n = __float_as_int(rn) - 0x4B400000;         // round(y)
    float f = y - (rn - 12582912.f);                 // frac in [-0.5, 0.5]
    float p = 1.3333558e-3f;
    p = fmaf(p, f, 9.6181290e-3f);
    p = fmaf(p, f, 5.5504108e-2f);
    p = fmaf(p, f, 2.4022650e-1f);
    p = fmaf(p, f, 6.9314718e-1f);
    p = fmaf(p, f, 1.0f);
    return __int_as_float(__float_as_int(p) + (n << 23));
}
#define EXP_SCALE 0.18033688011112042f   /* 0.125 * log2(e) */

// ---- packed A fragments: per-oct block = RB*128+8 u32 ----
template <int RB>
__device__ __forceinline__ void storeA(uint32_t* sA, int oct, int r, const float* f) {
    uint32_t* b = sA + oct * (RB * 128 + 8) + (r >> 4) * 128 + (r & 7) * 16 + ((r >> 3) & 1);
    int gs = r & 3;
#pragma unroll
    for (int p = 0; p < 4; p++) {
        int tq = p ^ gs;
        b[p * 4] = tf32_of(f[tq]);
        b[p * 4 + 2] = tf32_of(f[tq + 4]);
    }
}
template <int RB>
__device__ __forceinline__ uint4 loadA(const uint32_t* sA, int oct, int rb, int gid, int tig) {
    return *(const uint4*)(sA + oct * (RB * 128 + 8) + rb * 128 + gid * 16 +
                           ((tig ^ (gid & 3)) << 2));
}
// ---- packed B fragments: per-oct block = 8*S+8 u32, S = stride in uint2 units ----
template <int S>
__device__ __forceinline__ void storeB(uint32_t* sB, int oct, int c, const float* f) {
    uint32_t* b = sB + oct * (S * 8 + 8) + c * 2;
#pragma unroll
    for (int tq = 0; tq < 4; tq++)
        *(uint2*)(b + tq * S * 2) = make_uint2(tf32_of(f[tq]), tf32_of(f[tq + 4]));
}
template <int S>
__device__ __forceinline__ uint2 loadB(const uint32_t* sB, int oct, int tig, int c) {
    return *(const uint2*)(sB + oct * (S * 8 + 8) + (tig * S + c) * 2);
}

__device__ __forceinline__ void ld8(const float* p, bool ok, float* f) {
    float4 z = make_float4(0.f, 0.f, 0.f, 0.f);
    float4 x0 = ok ? *(const float4*)p : z;
    float4 x1 = ok ? *(const float4*)(p + 4) : z;
    f[0] = x0.x; f[1] = x0.y; f[2] = x0.z; f[3] = x0.w;
    f[4] = x1.x; f[5] = x1.y; f[6] = x1.z; f[7] = x1.w;
}

// ============================================================
// GEMM body: C[M,N] = A @ W^T (+bias). 128x128, BK=16, packed tf32.
// ============================================================
__device__ __forceinline__ void gemm_body(const float* __restrict__ A,
                                          const float* __restrict__ W,
                                          const float* __restrict__ bias,
                                          float* __restrict__ C,
                                          int M, int N, int K, int m0, int n0) {
    __shared__ __align__(16) uint32_t sA[2][2 * (8 * 128 + 8)];
    __shared__ __align__(16) uint32_t sB[2][2 * (132 * 8 + 8)];
    const int tid = threadIdx.x;
    const int lrow = tid >> 1, oct = tid & 1, lk = oct * 8;
    const int lane = tid & 31, wid = tid >> 5;
    const int rb0 = (wid >> 1) * 2, nB = (wid & 1) * 64;
    const int gid = lane >> 2, tig = lane & 3;

    float acc[2][8][4];
#pragma unroll
    for (int i = 0; i < 2; i++)
#pragma unroll
        for (int j = 0; j < 8; j++)
#pragma unroll
            for (int c = 0; c < 4; c++) acc[i][j][c] = 0.f;

    const bool av = (m0 + lrow) < M, wv = (n0 + lrow) < N;
    const float* Ar = A + (size_t)(m0 + lrow) * K + lk;
    const float* Wr = W + (size_t)(n0 + lrow) * K + lk;
    float fA[8], fB[8];
    ld8(Ar, av, fA);
    ld8(Wr, wv, fB);
    storeA<8>(sA[0], oct, lrow, fA);
    storeB<132>(sB[0], oct, lrow, fB);
    __syncthreads();

    const int nk = K / 16;
    for (int kt = 0; kt < nk; kt++) {
        const int cur = kt & 1;
        const bool more = (kt + 1) < nk;
        if (more) {
            ld8(Ar + (kt + 1) * 16, av, fA);
            ld8(Wr + (kt + 1) * 16, wv, fB);
        }
#pragma unroll
        for (int o = 0; o < 2; o++) {
            uint4 a0 = loadA<8>(sA[cur], o, rb0, gid, tig);
            uint4 a1 = loadA<8>(sA[cur], o, rb0 + 1, gid, tig);
#pragma unroll
            for (int nt = 0; nt < 8; nt++) {
                uint2 bv = loadB<132>(sB[cur], o, tig, nB + nt * 8 + gid);
                mma_p(acc[0][nt], a0, bv);
                mma_p(acc[1][nt], a1, bv);
            }
        }
        if (more) {
            storeA<8>(sA[cur ^ 1], oct, lrow, fA);
            storeB<132>(sB[cur ^ 1], oct, lrow, fB);
            __syncthreads();
        }
    }

#pragma unroll
    for (int mt = 0; mt < 2; mt++) {
        int r = m0 + (rb0 + mt) * 16 + gid;
#pragma unroll
        for (int nt = 0; nt < 8; nt++) {
            int c = n0 + nB + nt * 8 + 2 * tig;
            float b0v = bias ? bias[c] : 0.f;
            float b1v = bias ? bias[c + 1] : 0.f;
            if (r < M)
                *(float2*)(C + (size_t)r * N + c) =
                    make_float2(acc[mt][nt][0] + b0v, acc[mt][nt][1] + b1v);
            if (r + 8 < M)
                *(float2*)(C + (size_t)(r + 8) * N + c) =
                    make_float2(acc[mt][nt][2] + b0v, acc[mt][nt][3] + b1v);
        }
    }
}

__global__ __launch_bounds__(256, 2) void gemm_tc_nt(
    const float* __restrict__ A, const float* __restrict__ W,
    const float* __restrict__ bias, float* __restrict__ C, int M, int N, int K) {
    gemm_body(A, W, bias, C, M, N, K, blockIdx.y * 128, blockIdx.x * 128);
}

// QKV + pos projections in one launch. grid (32, 32).
__global__ __launch_bounds__(256, 2) void gemm_qkvp(
    const float* __restrict__ A, const float* __restrict__ rpe,
    const float* __restrict__ Wq, const float* __restrict__ Wk, const float* __restrict__ Wv,
    const float* __restrict__ Wp,
    const float* __restrict__ bq, const float* __restrict__ bk, const float* __restrict__ bv,
    float* __restrict__ Cq, float* __restrict__ Ck, float* __restrict__ Cv,
    float* __restrict__ Cp) {
    const int sel = blockIdx.x >> 3;
    if (sel == 3) {
        if (blockIdx.y >= 16) return;
        gemm_body(rpe, Wp, nullptr, Cp, Lc, Dc, Dc, blockIdx.y * 128, (blockIdx.x & 7) * 128);
        return;
    }
    const float* W = (sel == 0) ? Wq : (sel == 1) ? Wk : Wv;
    const float* bias = (sel == 0) ? bq : (sel == 1) ? bk : bv;
    float* C = (sel == 0) ? Cq : (sel == 1) ? Ck : Cv;
    gemm_body(A, W, bias, C, Bc * Tc, Dc, Dc, blockIdx.y * 128, (blockIdx.x & 7) * 128);
}

// ============================================================
// FUSED attention per (bh, 32-row q tile) — pipelined strips;
// exp on FMA pipe, folded into phase-4 pipeline.
// smem (u32): Sb 32*1028 | Au 8*264 | Av 8*264 | Bf 2*4416 | mx 32 | inv 32
// ============================================================
#define SB_STR 1028
#define AU_OFF (32 * SB_STR)
#define AV_OFF (AU_OFF + 8 * 264)
#define BF_OFF (AV_OFF + 8 * 264)
#define MX_OFF (BF_OFF + 2 * 4416)
#define INV_OFF (MX_OFF + 32)
#define FUSED_SMEM_BYTES ((INV_OFF + 32) * 4)

__global__ __launch_bounds__(256, 1) void fused_attn(
    const float* __restrict__ Q, const float* __restrict__ K,
    const float* __restrict__ P, const float* __restrict__ V,
    const float* __restrict__ u, const float* __restrict__ vb,
    float* __restrict__ probs, float* __restrict__ ctx) {
    extern __shared__ __align__(16) uint32_t su[];
    float* Sb = (float*)su;
    uint32_t* Au = su + AU_OFF;
    uint32_t* Av = su + AV_OFF;
    uint32_t* Bf0 = su + BF_OFF;
    float* mx_s = (float*)(su + MX_OFF);
    float* inv_s = (float*)(su + INV_OFF);

    const int t = threadIdx.x;
    const int bh = blockIdx.y, zb = bh >> 4, h = bh & 15;
    const int q0 = blockIdx.x * 32;
    const int lane = t & 31, w = t >> 5;
    const int mB = (w & 1) * 16, rbw = w & 1, nBf = (w >> 1) * 16;
    const int gid = lane >> 2, tig = lane & 3;

    // ---- stage q+u / q+v as packed A fragments (once) ----
    {
        int qr = t >> 3, o = t & 7;
        const float* qp = Q + ((size_t)(zb * Tc) + q0 + qr) * Dc + h * HSc + o * 8;
        const float* up = u + h * HSc + o * 8;
        const float* vp = vb + h * HSc + o * 8;
        float a[8], uu[8], fv[8];
        ld8(qp, true, a);
        ld8(up, true, uu);
        ld8(vp, true, fv);
        float fu2[8], fv2[8];
#pragma unroll
        for (int i = 0; i < 8; i++) { fu2[i] = a[i] + uu[i]; fv2[i] = a[i] + fv[i]; }
        storeA<2>(Au, o, qr, fu2);
        storeA<2>(Av, o, qr, fv2);
    }

    const int kr = t >> 2, qq = t & 3;
    float f0[8], f1[8];

    // ================= phase 1: ac = (q+u) K^T (pipelined) =================
    {
        const float* kp = K + ((size_t)(zb * Tc) + kr) * Dc + h * HSc + qq * 16;
        ld8(kp, true, f0);
        ld8(kp + 8, true, f1);
    }
    for (int j0 = 0; j0 < Tc; j0 += 64) {
        __syncthreads();
        storeB<68>(Bf0, 2 * qq, kr, f0);
        storeB<68>(Bf0, 2 * qq + 1, kr, f1);
        __syncthreads();
        if (j0 + 64 < Tc) {
            const float* kp = K + ((size_t)(zb * Tc) + j0 + 64 + kr) * Dc + h * HSc + qq * 16;
            ld8(kp, true, f0);
            ld8(kp + 8, true, f1);
        }

        float acc[2][4] = {{0.f, 0.f, 0.f, 0.f}, {0.f, 0.f, 0.f, 0.f}};
#pragma unroll
        for (int o = 0; o < 8; o++) {
            uint4 a = loadA<2>(Au, o, rbw, gid, tig);
#pragma unroll
            for (int nt = 0; nt < 2; nt++)
                mma_p(acc[nt], a, loadB<68>(Bf0, o, tig, nBf + nt * 8 + gid));
        }
#pragma unroll
        for (int nt = 0; nt < 2; nt++) {
            int col = j0 + nBf + nt * 8 + 2 * tig;
            *(float2*)&Sb[(mB + gid) * SB_STR + col] = make_float2(acc[nt][0], acc[nt][1]);
            *(float2*)&Sb[(mB + gid + 8) * SB_STR + col] = make_float2(acc[nt][2], acc[nt][3]);
        }
    }

    // ================= phase 2: bd band, scatter-add (pipelined) =================
    const int lStart = (Tc - 1) - (q0 + 31);
    {
        int l = lStart + kr;
        if (l < Lc) {
            const float* pp = P + (size_t)l * Dc + h * HSc + qq * 16;
            ld8(pp, true, f0);
            ld8(pp + 8, true, f1);
        } else {
#pragma unroll
            for (int i = 0; i < 8; i++) { f0[i] = 0.f; f1[i] = 0.f; }
        }
    }
    for (int it = 0; it < 17; it++) {
        int lBase = lStart + it * 64;
        __syncthreads();
        storeB<68>(Bf0, 2 * qq, kr, f0);
        storeB<68>(Bf0, 2 * qq + 1, kr, f1);
        __syncthreads();
        if (it + 1 < 17) {
            int l = lBase + 64 + kr;
            if (l < Lc) {
                const float* pp = P + (size_t)l * Dc + h * HSc + qq * 16;
                ld8(pp, true, f0);
                ld8(pp + 8, true, f1);
            } else {
#pragma unroll
                for (int i = 0; i < 8; i++) { f0[i] = 0.f; f1[i] = 0.f; }
            }
        }

        float acc[2][4] = {{0.f, 0.f, 0.f, 0.f}, {0.f, 0.f, 0.f, 0.f}};
#pragma unroll
        for (int o = 0; o < 8; o++) {
            uint4 a = loadA<2>(Av, o, rbw, gid, tig);
#pragma unroll
            for (int nt = 0; nt < 2; nt++)
                mma_p(acc[nt], a, loadB<68>(Bf0, o, tig, nBf + nt * 8 + gid));
        }
#pragma unroll
        for (int nt = 0; nt < 2; nt++) {
            int lc = lBase + nBf + nt * 8 + 2 * tig;
            int m = mB + gid;
            int j = (q0 + m) + lc - (Tc - 1);
            if (j >= 0 && j < Tc) Sb[m * SB_STR + j] += acc[nt][0];
            if (j + 1 >= 0 && j + 1 < Tc) Sb[m * SB_STR + j + 1] += acc[nt][1];
            int j2 = j + 8;
            if (j2 >= 0 && j2 < Tc) Sb[(m + 8) * SB_STR + j2] += acc[nt][2];
            if (j2 + 1 >= 0 && j2 + 1 < Tc) Sb[(m + 8) * SB_STR + j2 + 1] += acc[nt][3];
        }
    }
    __syncthreads();

    // ===== phase 3a: row max only =====
#pragma unroll
    for (int rr = 0; rr < 4; rr++) {
        int row_i = w * 4 + rr;
        const float* row = Sb + row_i * SB_STR;
        float mx = -3.4e38f;
        for (int c = lane; c < Tc; c += 32) mx = fmaxf(mx, row[c]);
#pragma unroll
        for (int o = 16; o; o >>= 1) mx = fmaxf(mx, __shfl_xor_sync(0xffffffffu, mx, o));
        if (lane == 0) mx_s[row_i] = mx;
    }
    __syncthreads();

    // ===== phase 4: exp (FMA pipe) folded into ctx pipeline =====
    const int row_e = t >> 3;
    const int ce = (t & 7) * 8;
    const float mxc = mx_s[row_e] * EXP_SCALE;   // y = x*S - mx*S
    float psum = 0.f;
    float* erow = Sb + row_e * SB_STR;

    // exp strip 0
    {
        float4 x0 = *(float4*)&erow[ce];
        float4 x1 = *(float4*)&erow[ce + 4];
        x0.x = fexp2(fmaf(x0.x, EXP_SCALE, -mxc)); x0.y = fexp2(fmaf(x0.y, EXP_SCALE, -mxc));
        x0.z = fexp2(fmaf(x0.z, EXP_SCALE, -mxc)); x0.w = fexp2(fmaf(x0.w, EXP_SCALE, -mxc));
        x1.x = fexp2(fmaf(x1.x, EXP_SCALE, -mxc)); x1.y = fexp2(fmaf(x1.y, EXP_SCALE, -mxc));
        x1.z = fexp2(fmaf(x1.z, EXP_SCALE, -mxc)); x1.w = fexp2(fmaf(x1.w, EXP_SCALE, -mxc));
        *(float4*)&erow[ce] = x0;
        *(float4*)&erow[ce + 4] = x1;
        psum += x0.x + x0.y + x0.z + x0.w + x1.x + x1.y + x1.z + x1.w;
    }

    uint32_t* Vt = Bf0;  // 64*72 u32
    float acc2[2][4] = {{0.f, 0.f, 0.f, 0.f}, {0.f, 0.f, 0.f, 0.f}};
    float fv[16];
    {
        const float* vp = V + ((size_t)(zb * Tc) + kr) * Dc + h * HSc + qq * 16;
        ld8(vp, true, fv);
        ld8(vp + 8, true, fv + 8);
    }
    for (int kc = 0; kc < Tc; kc += 64) {
        __syncthreads();
        uint32_t* dst = Vt + kr * 72 + qq * 16;
        *(uint4*)(dst + 0)  = make_uint4(tf32_of(fv[0]),  tf32_of(fv[1]),  tf32_of(fv[2]),  tf32_of(fv[3]));
        *(uint4*)(dst + 4)  = make_uint4(tf32_of(fv[4]),  tf32_of(fv[5]),  tf32_of(fv[6]),  tf32_of(fv[7]));
        *(uint4*)(dst + 8)  = make_uint4(tf32_of(fv[8]),  tf32_of(fv[9]),  tf32_of(fv[10]), tf32_of(fv[11]));
        *(uint4*)(dst + 12) = make_uint4(tf32_of(fv[12]), tf32_of(fv[13]), tf32_of(fv[14]), tf32_of(fv[15]));
        __syncthreads();
        if (kc + 64 < Tc) {
            const float* vp = V + ((size_t)(zb * Tc) + kc + 64 + kr) * Dc + h * HSc + qq * 16;
            ld8(vp, true, fv);
            ld8(vp + 8, true, fv + 8);
            float* ep = erow + kc + 64 + ce;
            float4 x0 = *(float4*)ep;
            float4 x1 = *(float4*)(ep + 4);
            x0.x = fexp2(fmaf(x0.x, EXP_SCALE, -mxc)); x0.y = fexp2(fmaf(x0.y, EXP_SCALE, -mxc));
            x0.z = fexp2(fmaf(x0.z, EXP_SCALE, -mxc)); x0.w = fexp2(fmaf(x0.w, EXP_SCALE, -mxc));
            x1.x = fexp2(fmaf(x1.x, EXP_SCALE, -mxc)); x1.y = fexp2(fmaf(x1.y, EXP_SCALE, -mxc));
            x1.z = fexp2(fmaf(x1.z, EXP_SCALE, -mxc)); x1.w = fexp2(fmaf(x1.w, EXP_SCALE, -mxc));
            *(float4*)ep = x0;
            *(float4*)(ep + 4) = x1;
            psum += x0.x + x0.y + x0.z + x0.w + x1.x + x1.y + x1.z + x1.w;
        }

        const float* ar0 = Sb + (mB + gid) * SB_STR + kc;
        const float* ar8 = ar0 + 8 * SB_STR;
#pragma unroll
        for (int o = 0; o < 8; o++) {
            uint4 a;
            a.x = tf32_of(ar0[o * 8 + tig]);
            a.y = tf32_of(ar8[o * 8 + tig]);
            a.z = tf32_of(ar0[o * 8 + tig + 4]);
            a.w = tf32_of(ar8[o * 8 + tig + 4]);
#pragma unroll
            for (int nt = 0; nt < 2; nt++) {
                int c = nBf + nt * 8 + gid;
                uint2 b;
                b.x = Vt[(o * 8 + tig) * 72 + c];
                b.y = Vt[(o * 8 + tig + 4) * 72 + c];
                mma_p(acc2[nt], a, b);
            }
        }
    }

    // ---- row-sum reduce over the 8 lanes sharing a row ----
#pragma unroll
    for (int o = 4; o; o >>= 1) psum += __shfl_xor_sync(0xffffffffu, psum, o);
    if ((lane & 7) == 0) inv_s[row_e] = 1.f / psum;
    __syncthreads();

    // ---- write probs = e * inv ----
    {
        float* pb = probs + ((size_t)bh << 20) + (size_t)q0 * Tc;
#pragma unroll 4
        for (int r = 0; r < 32; r++) {
            float iv = inv_s[r];
            float4 val = *(float4*)&Sb[r * SB_STR + 4 * t];
            val.x *= iv; val.y *= iv; val.z *= iv; val.w *= iv;
            *(float4*)(pb + (size_t)r * Tc + 4 * t) = val;
        }
    }

    // ---- ctx epilogue: scale by inv ----
    {
        int r = q0 + mB + gid;
        float iv0 = inv_s[mB + gid], iv8 = inv_s[mB + gid + 8];
#pragma unroll
        for (int nt = 0; nt < 2; nt++) {
            int c = nBf + nt * 8 + 2 * tig;
            *(float2*)(ctx + ((size_t)(zb * Tc) + r) * Dc + h * HSc + c) =
                make_float2(acc2[nt][0] * iv0, acc2[nt][1] * iv0);
            *(float2*)(ctx + ((size_t)(zb * Tc) + r + 8) * Dc + h * HSc + c) =
                make_float2(acc2[nt][2] * iv8, acc2[nt][3] * iv8);
        }
    }
}

// ============================================================
extern "C" void kernel_launch(void* const* d_in, const int* in_sizes, int n_in,
                              void* d_out, int out_size) {
    const float* hs  = (const float*)d_in[0];
    const float* rpe = (const float*)d_in[1];
    const float* Wq  = (const float*)d_in[2];
    const float* bq  = (const float*)d_in[3];
    const float* Wk  = (const float*)d_in[4];
    const float* bk  = (const float*)d_in[5];
    const float* Wv  = (const float*)d_in[6];
    const float* bv  = (const float*)d_in[7];
    const float* Wo  = (const float*)d_in[8];
    const float* bo  = (const float*)d_in[9];
    const float* Wp  = (const float*)d_in[10];
    const float* pu  = (const float*)d_in[11];
    const float* pvb = (const float*)d_in[12];

    float* out = (float*)d_out;
    float* S   = out + (size_t)Bc * Tc * Dc;

    float *pq, *pk, *pv, *pp, *pctx;
    cudaGetSymbolAddress((void**)&pq,   g_q);
    cudaGetSymbolAddress((void**)&pk,   g_k);
    cudaGetSymbolAddress((void**)&pv,   g_v);
    cudaGetSymbolAddress((void**)&pp,   g_p);
    cudaGetSymbolAddress((void**)&pctx, g_ctx);

    cudaFuncSetAttribute(fused_attn, cudaFuncAttributeMaxDynamicSharedMemorySize,
                         FUSED_SMEM_BYTES);

    dim3 thr(256);
    gemm_qkvp<<<dim3(32, 32), thr>>>(hs, rpe, Wq, Wk, Wv, Wp, bq, bk, bv,
                                     pq, pk, pv, pp);

    fused_attn<<<dim3(Tc / 32, Bc * Hc), thr, FUSED_SMEM_BYTES>>>(
        pq, pk, pp, pv, pu, pvb, S, pctx);

    gemm_tc_nt<<<dim3(8, 32), thr>>>(pctx, Wo, bo, out, Bc * Tc, Dc, Dc);
}

// round 12
// speedup vs baseline: 1.0462x; 1.0462x over previous
#include <cuda_runtime.h>
#include <math.h>
#include <stdint.h>

#define Bc 4
#define Tc 1024
#define Dc 1024
#define Hc 16
#define HSc 64
#define Lc 2047

__device__ float g_q[Bc * Tc * Dc];
__device__ float g_k[Bc * Tc * Dc];
__device__ float g_v[Bc * Tc * Dc];
__device__ float g_p[Lc * Dc];
__device__ float g_ctx[Bc * Tc * Dc];

__device__ __forceinline__ uint32_t tf32_of(float x) {
    uint32_t r;
    asm("cvt.rna.tf32.f32 %0, %1;" : "=r"(r) : "f"(x));
    return r;
}
__device__ __forceinline__ void mma_p(float* d, uint4 a, uint2 b) {
    asm volatile(
        "mma.sync.aligned.m16n8k8.row.col.f32.tf32.tf32.f32 "
        "{%0,%1,%2,%3},{%4,%5,%6,%7},{%8,%9},{%0,%1,%2,%3};"
        : "+f"(d[0]), "+f"(d[1]), "+f"(d[2]), "+f"(d[3])
        : "r"(a.x), "r"(a.y), "r"(a.z), "r"(a.w), "r"(b.x), "r"(b.y));
}

// FMA-pipe exp: 2^y via magic-round + degree-5 poly (no MUFU).
__device__ __forceinline__ float fexp2(float y) {
    y = fmaxf(y, -100.f);
    float rn = y + 12582912.f;
    int n = __float_as_int(rn) - 0x4B400000;
    float f = y - (rn - 12582912.f);
    float p = 1.3333558e-3f;
    p = fmaf(p, f, 9.6181290e-3f);
    p = fmaf(p, f, 5.5504108e-2f);
    p = fmaf(p, f, 2.4022650e-1f);
    p = fmaf(p, f, 6.9314718e-1f);
    p = fmaf(p, f, 1.0f);
    return __int_as_float(__float_as_int(p) + (n << 23));
}
#define EXP_SCALE 0.18033688011112042f   /* 0.125 * log2(e) */

// ---- packed A fragments: per-oct block = RB*128+8 u32 ----
template <int RB>
__device__ __forceinline__ void storeA(uint32_t* sA, int oct, int r, const float* f) {
    uint32_t* b = sA + oct * (RB * 128 + 8) + (r >> 4) * 128 + (r & 7) * 16 + ((r >> 3) & 1);
    int gs = r & 3;
#pragma unroll
    for (int p = 0; p < 4; p++) {
        int tq = p ^ gs;
        b[p * 4] = tf32_of(f[tq]);
        b[p * 4 + 2] = tf32_of(f[tq + 4]);
    }
}
template <int RB>
__device__ __forceinline__ uint4 loadA(const uint32_t* sA, int oct, int rb, int gid, int tig) {
    return *(const uint4*)(sA + oct * (RB * 128 + 8) + rb * 128 + gid * 16 +
                           ((tig ^ (gid & 3)) << 2));
}
// ---- packed B fragments: per-oct block = 8*S+8 u32, S = stride in uint2 units ----
template <int S>
__device__ __forceinline__ void storeB(uint32_t* sB, int oct, int c, const float* f) {
    uint32_t* b = sB + oct * (S * 8 + 8) + c * 2;
#pragma unroll
    for (int tq = 0; tq < 4; tq++)
        *(uint2*)(b + tq * S * 2) = make_uint2(tf32_of(f[tq]), tf32_of(f[tq + 4]));
}
template <int S>
__device__ __forceinline__ uint2 loadB(const uint32_t* sB, int oct, int tig, int c) {
    return *(const uint2*)(sB + oct * (S * 8 + 8) + (tig * S + c) * 2);
}

__device__ __forceinline__ void ld8(const float* p, bool ok, float* f) {
    float4 z = make_float4(0.f, 0.f, 0.f, 0.f);
    float4 x0 = ok ? *(const float4*)p : z;
    float4 x1 = ok ? *(const float4*)(p + 4) : z;
    f[0] = x0.x; f[1] = x0.y; f[2] = x0.z; f[3] = x0.w;
    f[4] = x1.x; f[5] = x1.y; f[6] = x1.z; f[7] = x1.w;
}

// ============================================================
// GEMM body: C[M,N] = A @ W^T (+bias). 128x128, BK=16, packed tf32.
// ============================================================
__device__ __forceinline__ void gemm_body(const float* __restrict__ A,
                                          const float* __restrict__ W,
                                          const float* __restrict__ bias,
                                          float* __restrict__ C,
                                          int M, int N, int K, int m0, int n0) {
    __shared__ __align__(16) uint32_t sA[2][2 * (8 * 128 + 8)];
    __shared__ __align__(16) uint32_t sB[2][2 * (132 * 8 + 8)];
    const int tid = threadIdx.x;
    const int lrow = tid >> 1, oct = tid & 1, lk = oct * 8;
    const int lane = tid & 31, wid = tid >> 5;
    const int rb0 = (wid >> 1) * 2, nB = (wid & 1) * 64;
    const int gid = lane >> 2, tig = lane & 3;

    float acc[2][8][4];
#pragma unroll
    for (int i = 0; i < 2; i++)
#pragma unroll
        for (int j = 0; j < 8; j++)
#pragma unroll
            for (int c = 0; c < 4; c++) acc[i][j][c] = 0.f;

    const bool av = (m0 + lrow) < M, wv = (n0 + lrow) < N;
    const float* Ar = A + (size_t)(m0 + lrow) * K + lk;
    const float* Wr = W + (size_t)(n0 + lrow) * K + lk;
    float fA[8], fB[8];
    ld8(Ar, av, fA);
    ld8(Wr, wv, fB);
    storeA<8>(sA[0], oct, lrow, fA);
    storeB<132>(sB[0], oct, lrow, fB);
    __syncthreads();

    const int nk = K / 16;
    for (int kt = 0; kt < nk; kt++) {
        const int cur = kt & 1;
        const bool more = (kt + 1) < nk;
        if (more) {
            ld8(Ar + (kt + 1) * 16, av, fA);
            ld8(Wr + (kt + 1) * 16, wv, fB);
        }
#pragma unroll
        for (int o = 0; o < 2; o++) {
            uint4 a0 = loadA<8>(sA[cur], o, rb0, gid, tig);
            uint4 a1 = loadA<8>(sA[cur], o, rb0 + 1, gid, tig);
#pragma unroll
            for (int nt = 0; nt < 8; nt++) {
                uint2 bv = loadB<132>(sB[cur], o, tig, nB + nt * 8 + gid);
                mma_p(acc[0][nt], a0, bv);
                mma_p(acc[1][nt], a1, bv);
            }
        }
        if (more) {
            storeA<8>(sA[cur ^ 1], oct, lrow, fA);
            storeB<132>(sB[cur ^ 1], oct, lrow, fB);
            __syncthreads();
        }
    }

#pragma unroll
    for (int mt = 0; mt < 2; mt++) {
        int r = m0 + (rb0 + mt) * 16 + gid;
#pragma unroll
        for (int nt = 0; nt < 8; nt++) {
            int c = n0 + nB + nt * 8 + 2 * tig;
            float b0v = bias ? bias[c] : 0.f;
            float b1v = bias ? bias[c + 1] : 0.f;
            if (r < M)
                *(float2*)(C + (size_t)r * N + c) =
                    make_float2(acc[mt][nt][0] + b0v, acc[mt][nt][1] + b1v);
            if (r + 8 < M)
                *(float2*)(C + (size_t)(r + 8) * N + c) =
                    make_float2(acc[mt][nt][2] + b0v, acc[mt][nt][3] + b1v);
        }
    }
}

__global__ __launch_bounds__(256, 2) void gemm_tc_nt(
    const float* __restrict__ A, const float* __restrict__ W,
    const float* __restrict__ bias, float* __restrict__ C, int M, int N, int K) {
    gemm_body(A, W, bias, C, M, N, K, blockIdx.y * 128, blockIdx.x * 128);
}

// QKV + pos projections in one launch. grid (32, 32).
__global__ __launch_bounds__(256, 2) void gemm_qkvp(
    const float* __restrict__ A, const float* __restrict__ rpe,
    const float* __restrict__ Wq, const float* __restrict__ Wk, const float* __restrict__ Wv,
    const float* __restrict__ Wp,
    const float* __restrict__ bq, const float* __restrict__ bk, const float* __restrict__ bv,
    float* __restrict__ Cq, float* __restrict__ Ck, float* __restrict__ Cv,
    float* __restrict__ Cp) {
    const int sel = blockIdx.x >> 3;
    if (sel == 3) {
        if (blockIdx.y >= 16) return;
        gemm_body(rpe, Wp, nullptr, Cp, Lc, Dc, Dc, blockIdx.y * 128, (blockIdx.x & 7) * 128);
        return;
    }
    const float* W = (sel == 0) ? Wq : (sel == 1) ? Wk : Wv;
    const float* bias = (sel == 0) ? bq : (sel == 1) ? bk : bv;
    float* C = (sel == 0) ? Cq : (sel == 1) ? Ck : Cv;
    gemm_body(A, W, bias, C, Bc * Tc, Dc, Dc, blockIdx.y * 128, (blockIdx.x & 7) * 128);
}

// ============================================================
// FUSED attention per (bh, 32-row q tile) — double-buffered strips,
// one barrier per strip, hoisted A fragments, FMA exp in phase 4.
// smem (u32): Sb 32*1028 | Au 8*264 | Av 8*264 | Bf 2*4608 | mx 32 | inv 32
// ============================================================
#define SB_STR 1028
#define AU_OFF (32 * SB_STR)
#define AV_OFF (AU_OFF + 8 * 264)
#define BF_OFF (AV_OFF + 8 * 264)
#define BF_STR 4608
#define MX_OFF (BF_OFF + 2 * BF_STR)
#define INV_OFF (MX_OFF + 32)
#define FUSED_SMEM_BYTES ((INV_OFF + 32) * 4)

__global__ __launch_bounds__(256, 1) void fused_attn(
    const float* __restrict__ Q, const float* __restrict__ K,
    const float* __restrict__ P, const float* __restrict__ V,
    const float* __restrict__ u, const float* __restrict__ vb,
    float* __restrict__ probs, float* __restrict__ ctx) {
    extern __shared__ __align__(16) uint32_t su[];
    float* Sb = (float*)su;
    uint32_t* Au = su + AU_OFF;
    uint32_t* Av = su + AV_OFF;
    uint32_t* Bf = su + BF_OFF;
    float* mx_s = (float*)(su + MX_OFF);
    float* inv_s = (float*)(su + INV_OFF);

    const int t = threadIdx.x;
    const int bh = blockIdx.y, zb = bh >> 4, h = bh & 15;
    const int q0 = blockIdx.x * 32;
    const int lane = t & 31, w = t >> 5;
    const int mB = (w & 1) * 16, rbw = w & 1, nBf = (w >> 1) * 16;
    const int gid = lane >> 2, tig = lane & 3;

    // ---- stage q+u / q+v as packed A fragments (once) ----
    {
        int qr = t >> 3, o = t & 7;
        const float* qp = Q + ((size_t)(zb * Tc) + q0 + qr) * Dc + h * HSc + o * 8;
        const float* up = u + h * HSc + o * 8;
        const float* vp = vb + h * HSc + o * 8;
        float a[8], uu[8], fv[8];
        ld8(qp, true, a);
        ld8(up, true, uu);
        ld8(vp, true, fv);
        float fu2[8], fv2[8];
#pragma unroll
        for (int i = 0; i < 8; i++) { fu2[i] = a[i] + uu[i]; fv2[i] = a[i] + fv[i]; }
        storeA<2>(Au, o, qr, fu2);
        storeA<2>(Av, o, qr, fv2);
    }

    const int kr = t >> 2, qq = t & 3;
    float f0[8], f1[8];
    uint4 aF[8];

    // ================= phase 1: ac = (q+u) K^T =================
    {
        const float* kp = K + ((size_t)(zb * Tc) + kr) * Dc + h * HSc + qq * 16;
        ld8(kp, true, f0);
        ld8(kp + 8, true, f1);
        storeB<68>(Bf, 2 * qq, kr, f0);
        storeB<68>(Bf, 2 * qq + 1, kr, f1);
    }
    __syncthreads();   // Bf[0] staged; Au/Av staged
#pragma unroll
    for (int o = 0; o < 8; o++) aF[o] = loadA<2>(Au, o, rbw, gid, tig);
    {
        const float* kp = K + ((size_t)(zb * Tc) + 64 + kr) * Dc + h * HSc + qq * 16;
        ld8(kp, true, f0);
        ld8(kp + 8, true, f1);
    }
    for (int s = 0; s < 16; s++) {
        const uint32_t* bufc = Bf + (s & 1) * BF_STR;
        if (s + 1 < 16) {
            uint32_t* bufn = Bf + ((s + 1) & 1) * BF_STR;
            storeB<68>(bufn, 2 * qq, kr, f0);
            storeB<68>(bufn, 2 * qq + 1, kr, f1);
            if (s + 2 < 16) {
                const float* kp =
                    K + ((size_t)(zb * Tc) + (s + 2) * 64 + kr) * Dc + h * HSc + qq * 16;
                ld8(kp, true, f0);
                ld8(kp + 8, true, f1);
            }
        }
        float acc[2][4] = {{0.f, 0.f, 0.f, 0.f}, {0.f, 0.f, 0.f, 0.f}};
#pragma unroll
        for (int o = 0; o < 8; o++)
#pragma unroll
            for (int nt = 0; nt < 2; nt++)
                mma_p(acc[nt], aF[o], loadB<68>(bufc, o, tig, nBf + nt * 8 + gid));
#pragma unroll
        for (int nt = 0; nt < 2; nt++) {
            int col = s * 64 + nBf + nt * 8 + 2 * tig;
            *(float2*)&Sb[(mB + gid) * SB_STR + col] = make_float2(acc[nt][0], acc[nt][1]);
            *(float2*)&Sb[(mB + gid + 8) * SB_STR + col] = make_float2(acc[nt][2], acc[nt][3]);
        }
        __syncthreads();
    }

    // ================= phase 2: bd band, scatter-add =================
    const int lStart = (Tc - 1) - (q0 + 31);
#pragma unroll
    for (int o = 0; o < 8; o++) aF[o] = loadA<2>(Av, o, rbw, gid, tig);
    {
        int l = lStart + kr;
        if (l < Lc) {
            const float* pp = P + (size_t)l * Dc + h * HSc + qq * 16;
            ld8(pp, true, f0);
            ld8(pp + 8, true, f1);
        } else {
#pragma unroll
            for (int i = 0; i < 8; i++) { f0[i] = 0.f; f1[i] = 0.f; }
        }
        storeB<68>(Bf, 2 * qq, kr, f0);
        storeB<68>(Bf, 2 * qq + 1, kr, f1);
    }
    __syncthreads();
    {
        int l = lStart + 64 + kr;
        if (l < Lc) {
            const float* pp = P + (size_t)l * Dc + h * HSc + qq * 16;
            ld8(pp, true, f0);
            ld8(pp + 8, true, f1);
        } else {
#pragma unroll
            for (int i = 0; i < 8; i++) { f0[i] = 0.f; f1[i] = 0.f; }
        }
    }
    for (int s = 0; s < 17; s++) {
        int lBase = lStart + s * 64;
        const uint32_t* bufc = Bf + (s & 1) * BF_STR;
        if (s + 1 < 17) {
            uint32_t* bufn = Bf + ((s + 1) & 1) * BF_STR;
            storeB<68>(bufn, 2 * qq, kr, f0);
            storeB<68>(bufn, 2 * qq + 1, kr, f1);
            if (s + 2 < 17) {
                int l = lStart + (s + 2) * 64 + kr;
                if (l < Lc) {
                    const float* pp = P + (size_t)l * Dc + h * HSc + qq * 16;
                    ld8(pp, true, f0);
                    ld8(pp + 8, true, f1);
                } else {
#pragma unroll
                    for (int i = 0; i < 8; i++) { f0[i] = 0.f; f1[i] = 0.f; }
                }
            }
        }
        float acc[2][4] = {{0.f, 0.f, 0.f, 0.f}, {0.f, 0.f, 0.f, 0.f}};
#pragma unroll
        for (int o = 0; o < 8; o++)
#pragma unroll
            for (int nt = 0; nt < 2; nt++)
                mma_p(acc[nt], aF[o], loadB<68>(bufc, o, tig, nBf + nt * 8 + gid));
#pragma unroll
        for (int nt = 0; nt < 2; nt++) {
            int lc = lBase + nBf + nt * 8 + 2 * tig;
            int m = mB + gid;
            int j = (q0 + m) + lc - (Tc - 1);
            if (j >= 0 && j < Tc) Sb[m * SB_STR + j] += acc[nt][0];
            if (j + 1 >= 0 && j + 1 < Tc) Sb[m * SB_STR + j + 1] += acc[nt][1];
            int j2 = j + 8;
            if (j2 >= 0 && j2 < Tc) Sb[(m + 8) * SB_STR + j2] += acc[nt][2];
            if (j2 + 1 >= 0 && j2 + 1 < Tc) Sb[(m + 8) * SB_STR + j2 + 1] += acc[nt][3];
        }
        __syncthreads();
    }

    // ===== phase 3a: row max only =====
#pragma unroll
    for (int rr = 0; rr < 4; rr++) {
        int row_i = w * 4 + rr;
        const float* row = Sb + row_i * SB_STR;
        float mx = -3.4e38f;
        for (int c = lane; c < Tc; c += 32) mx = fmaxf(mx, row[c]);
#pragma unroll
        for (int o = 16; o; o >>= 1) mx = fmaxf(mx, __shfl_xor_sync(0xffffffffu, mx, o));
        if (lane == 0) mx_s[row_i] = mx;
    }
    __syncthreads();

    // ===== phase 4: exp (FMA pipe) + ctx, double-buffered V =====
    const int row_e = t >> 3;
    const int ce = (t & 7) * 8;
    const float mxc = mx_s[row_e] * EXP_SCALE;
    float psum = 0.f;
    float* erow = Sb + row_e * SB_STR;

    // exp strip 0
    {
        float4 x0 = *(float4*)&erow[ce];
        float4 x1 = *(float4*)&erow[ce + 4];
        x0.x = fexp2(fmaf(x0.x, EXP_SCALE, -mxc)); x0.y = fexp2(fmaf(x0.y, EXP_SCALE, -mxc));
        x0.z = fexp2(fmaf(x0.z, EXP_SCALE, -mxc)); x0.w = fexp2(fmaf(x0.w, EXP_SCALE, -mxc));
        x1.x = fexp2(fmaf(x1.x, EXP_SCALE, -mxc)); x1.y = fexp2(fmaf(x1.y, EXP_SCALE, -mxc));
        x1.z = fexp2(fmaf(x1.z, EXP_SCALE, -mxc)); x1.w = fexp2(fmaf(x1.w, EXP_SCALE, -mxc));
        *(float4*)&erow[ce] = x0;
        *(float4*)&erow[ce + 4] = x1;
        psum += x0.x + x0.y + x0.z + x0.w + x1.x + x1.y + x1.z + x1.w;
    }

    float acc2[2][4] = {{0.f, 0.f, 0.f, 0.f}, {0.f, 0.f, 0.f, 0.f}};
    float fv[16];
    {
        const float* vp = V + ((size_t)(zb * Tc) + kr) * Dc + h * HSc + qq * 16;
        ld8(vp, true, fv);
        ld8(vp + 8, true, fv + 8);
        uint32_t* dst = Bf + kr * 72 + qq * 16;
        *(uint4*)(dst + 0)  = make_uint4(tf32_of(fv[0]),  tf32_of(fv[1]),  tf32_of(fv[2]),  tf32_of(fv[3]));
        *(uint4*)(dst + 4)  = make_uint4(tf32_of(fv[4]),  tf32_of(fv[5]),  tf32_of(fv[6]),  tf32_of(fv[7]));
        *(uint4*)(dst + 8)  = make_uint4(tf32_of(fv[8]),  tf32_of(fv[9]),  tf32_of(fv[10]), tf32_of(fv[11]));
        *(uint4*)(dst + 12) = make_uint4(tf32_of(fv[12]), tf32_of(fv[13]), tf32_of(fv[14]), tf32_of(fv[15]));
    }
    __syncthreads();
    {
        const float* vp = V + ((size_t)(zb * Tc) + 64 + kr) * Dc + h * HSc + qq * 16;
        ld8(vp, true, fv);
        ld8(vp + 8, true, fv + 8);
    }
    for (int s = 0; s < 16; s++) {
        const uint32_t* Vtc = Bf + (s & 1) * BF_STR;
        if (s + 1 < 16) {
            uint32_t* Vtn = Bf + ((s + 1) & 1) * BF_STR;
            uint32_t* dst = Vtn + kr * 72 + qq * 16;
            *(uint4*)(dst + 0)  = make_uint4(tf32_of(fv[0]),  tf32_of(fv[1]),  tf32_of(fv[2]),  tf32_of(fv[3]));
            *(uint4*)(dst + 4)  = make_uint4(tf32_of(fv[4]),  tf32_of(fv[5]),  tf32_of(fv[6]),  tf32_of(fv[7]));
            *(uint4*)(dst + 8)  = make_uint4(tf32_of(fv[8]),  tf32_of(fv[9]),  tf32_of(fv[10]), tf32_of(fv[11]));
            *(uint4*)(dst + 12) = make_uint4(tf32_of(fv[12]), tf32_of(fv[13]), tf32_of(fv[14]), tf32_of(fv[15]));
            if (s + 2 < 16) {
                const float* vp =
                    V + ((size_t)(zb * Tc) + (s + 2) * 64 + kr) * Dc + h * HSc + qq * 16;
                ld8(vp, true, fv);
                ld8(vp + 8, true, fv + 8);
            }
            // exp strip s+1 (read by MMA at iteration s+1, after the sync below)
            float* ep = erow + (s + 1) * 64 + ce;
            float4 x0 = *(float4*)ep;
            float4 x1 = *(float4*)(ep + 4);
            x0.x = fexp2(fmaf(x0.x, EXP_SCALE, -mxc)); x0.y = fexp2(fmaf(x0.y, EXP_SCALE, -mxc));
            x0.z = fexp2(fmaf(x0.z, EXP_SCALE, -mxc)); x0.w = fexp2(fmaf(x0.w, EXP_SCALE, -mxc));
            x1.x = fexp2(fmaf(x1.x, EXP_SCALE, -mxc)); x1.y = fexp2(fmaf(x1.y, EXP_SCALE, -mxc));
            x1.z = fexp2(fmaf(x1.z, EXP_SCALE, -mxc)); x1.w = fexp2(fmaf(x1.w, EXP_SCALE, -mxc));
            *(float4*)ep = x0;
            *(float4*)(ep + 4) = x1;
            psum += x0.x + x0.y + x0.z + x0.w + x1.x + x1.y + x1.z + x1.w;
        }

        const float* ar0 = Sb + (mB + gid) * SB_STR + s * 64;
        const float* ar8 = ar0 + 8 * SB_STR;
#pragma unroll
        for (int o = 0; o < 8; o++) {
            uint4 a;
            a.x = tf32_of(ar0[o * 8 + tig]);
            a.y = tf32_of(ar8[o * 8 + tig]);
            a.z = tf32_of(ar0[o * 8 + tig + 4]);
            a.w = tf32_of(ar8[o * 8 + tig + 4]);
#pragma unroll
            for (int nt = 0; nt < 2; nt++) {
                int c = nBf + nt * 8 + gid;
                uint2 b;
                b.x = Vtc[(o * 8 + tig) * 72 + c];
                b.y = Vtc[(o * 8 + tig + 4) * 72 + c];
                mma_p(acc2[nt], a, b);
            }
        }
        __syncthreads();
    }

    // ---- row-sum reduce over the 8 lanes sharing a row ----
#pragma unroll
    for (int o = 4; o; o >>= 1) psum += __shfl_xor_sync(0xffffffffu, psum, o);
    if ((lane & 7) == 0) inv_s[row_e] = 1.f / psum;
    __syncthreads();

    // ---- write probs = e * inv ----
    {
        float* pb = probs + ((size_t)bh << 20) + (size_t)q0 * Tc;
#pragma unroll 4
        for (int r = 0; r < 32; r++) {
            float iv = inv_s[r];
            float4 val = *(float4*)&Sb[r * SB_STR + 4 * t];
            val.x *= iv; val.y *= iv; val.z *= iv; val.w *= iv;
            *(float4*)(pb + (size_t)r * Tc + 4 * t) = val;
        }
    }

    // ---- ctx epilogue: scale by inv ----
    {
        int r = q0 + mB + gid;
        float iv0 = inv_s[mB + gid], iv8 = inv_s[mB + gid + 8];
#pragma unroll
        for (int nt = 0; nt < 2; nt++) {
            int c = nBf + nt * 8 + 2 * tig;
            *(float2*)(ctx + ((size_t)(zb * Tc) + r) * Dc + h * HSc + c) =
                make_float2(acc2[nt][0] * iv0, acc2[nt][1] * iv0);
            *(float2*)(ctx + ((size_t)(zb * Tc) + r + 8) * Dc + h * HSc + c) =
                make_float2(acc2[nt][2] * iv8, acc2[nt][3] * iv8);
        }
    }
}

// ============================================================
extern "C" void kernel_launch(void* const* d_in, const int* in_sizes, int n_in,
                              void* d_out, int out_size) {
    const float* hs  = (const float*)d_in[0];
    const float* rpe = (const float*)d_in[1];
    const float* Wq  = (const float*)d_in[2];
    const float* bq  = (const float*)d_in[3];
    const float* Wk  = (const float*)d_in[4];
    const float* bk  = (const float*)d_in[5];
    const float* Wv  = (const float*)d_in[6];
    const float* bv  = (const float*)d_in[7];
    const float* Wo  = (const float*)d_in[8];
    const float* bo  = (const float*)d_in[9];
    const float* Wp  = (const float*)d_in[10];
    const float* pu  = (const float*)d_in[11];
    const float* pvb = (const float*)d_in[12];

    float* out = (float*)d_out;
    float* S   = out + (size_t)Bc * Tc * Dc;

    float *pq, *pk, *pv, *pp, *pctx;
    cudaGetSymbolAddress((void**)&pq,   g_q);
    cudaGetSymbolAddress((void**)&pk,   g_k);
    cudaGetSymbolAddress((void**)&pv,   g_v);
    cudaGetSymbolAddress((void**)&pp,   g_p);
    cudaGetSymbolAddress((void**)&pctx, g_ctx);

    cudaFuncSetAttribute(fused_attn, cudaFuncAttributeMaxDynamicSharedMemorySize,
                         FUSED_SMEM_BYTES);

    dim3 thr(256);
    gemm_qkvp<<<dim3(32, 32), thr>>>(hs, rpe, Wq, Wk, Wv, Wp, bq, bk, bv,
                                     pq, pk, pv, pp);

    fused_attn<<<dim3(Tc / 32, Bc * Hc), thr, FUSED_SMEM_BYTES>>>(
        pq, pk, pp, pv, pu, pvb, S, pctx);

    gemm_tc_nt<<<dim3(8, 32), thr>>>(pctx, Wo, bo, out, Bc * Tc, Dc, Dc);
}

// round 13
// speedup vs baseline: 1.1417x; 1.0913x over previous
#include <cuda_runtime.h>
#include <math.h>
#include <stdint.h>

#define Bc 4
#define Tc 1024
#define Dc 1024
#define Hc 16
#define HSc 64
#define Lc 2047

__device__ float g_q[Bc * Tc * Dc];
__device__ float g_k[Bc * Tc * Dc];
__device__ float g_v[Bc * Tc * Dc];
__device__ float g_p[Lc * Dc];
__device__ float g_ctx[Bc * Tc * Dc];

__device__ __forceinline__ uint32_t tf32_of(float x) {
    uint32_t r;
    asm("cvt.rna.tf32.f32 %0, %1;" : "=r"(r) : "f"(x));
    return r;
}
__device__ __forceinline__ void mma_p(float* d, uint4 a, uint2 b) {
    asm volatile(
        "mma.sync.aligned.m16n8k8.row.col.f32.tf32.tf32.f32 "
        "{%0,%1,%2,%3},{%4,%5,%6,%7},{%8,%9},{%0,%1,%2,%3};"
        : "+f"(d[0]), "+f"(d[1]), "+f"(d[2]), "+f"(d[3])
        : "r"(a.x), "r"(a.y), "r"(a.z), "r"(a.w), "r"(b.x), "r"(b.y));
}

// FMA-pipe exp: 2^y via magic-round + degree-5 poly.
__device__ __forceinline__ float fexp2(float y) {
    y = fmaxf(y, -100.f);
    float rn = y + 12582912.f;
    int n = __float_as_int(rn) - 0x4B400000;
    float f = y - (rn - 12582912.f);
    float p = 1.3333558e-3f;
    p = fmaf(p, f, 9.6181290e-3f);
    p = fmaf(p, f, 5.5504108e-2f);
    p = fmaf(p, f, 2.4022650e-1f);
    p = fmaf(p, f, 6.9314718e-1f);
    p = fmaf(p, f, 1.0f);
    return __int_as_float(__float_as_int(p) + (n << 23));
}
#define EXP_SCALE 0.18033688011112042f   /* 0.125 * log2(e) */

// ---- packed A fragments ----
template <int RB>
__device__ __forceinline__ void storeA(uint32_t* sA, int oct, int r, const float* f) {
    uint32_t* b = sA + oct * (RB * 128 + 8) + (r >> 4) * 128 + (r & 7) * 16 + ((r >> 3) & 1);
    int gs = r & 3;
#pragma unroll
    for (int p = 0; p < 4; p++) {
        int tq = p ^ gs;
        b[p * 4] = tf32_of(f[tq]);
        b[p * 4 + 2] = tf32_of(f[tq + 4]);
    }
}
template <int RB>
__device__ __forceinline__ uint4 loadA(const uint32_t* sA, int oct, int rb, int gid, int tig) {
    return *(const uint4*)(sA + oct * (RB * 128 + 8) + rb * 128 + gid * 16 +
                           ((tig ^ (gid & 3)) << 2));
}
// ---- packed B fragments ----
template <int S>
__device__ __forceinline__ void storeB(uint32_t* sB, int oct, int c, const float* f) {
    uint32_t* b = sB + oct * (S * 8 + 8) + c * 2;
#pragma unroll
    for (int tq = 0; tq < 4; tq++)
        *(uint2*)(b + tq * S * 2) = make_uint2(tf32_of(f[tq]), tf32_of(f[tq + 4]));
}
template <int S>
__device__ __forceinline__ uint2 loadB(const uint32_t* sB, int oct, int tig, int c) {
    return *(const uint2*)(sB + oct * (S * 8 + 8) + (tig * S + c) * 2);
}

__device__ __forceinline__ void ld8(const float* p, bool ok, float* f) {
    float4 z = make_float4(0.f, 0.f, 0.f, 0.f);
    float4 x0 = ok ? *(const float4*)p : z;
    float4 x1 = ok ? *(const float4*)(p + 4) : z;
    f[0] = x0.x; f[1] = x0.y; f[2] = x0.z; f[3] = x0.w;
    f[4] = x1.x; f[5] = x1.y; f[6] = x1.z; f[7] = x1.w;
}

// ============================================================
// GEMM body (unchanged, proven)
// ============================================================
__device__ __forceinline__ void gemm_body(const float* __restrict__ A,
                                          const float* __restrict__ W,
                                          const float* __restrict__ bias,
                                          float* __restrict__ C,
                                          int M, int N, int K, int m0, int n0) {
    __shared__ __align__(16) uint32_t sA[2][2 * (8 * 128 + 8)];
    __shared__ __align__(16) uint32_t sB[2][2 * (132 * 8 + 8)];
    const int tid = threadIdx.x;
    const int lrow = tid >> 1, oct = tid & 1, lk = oct * 8;
    const int lane = tid & 31, wid = tid >> 5;
    const int rb0 = (wid >> 1) * 2, nB = (wid & 1) * 64;
    const int gid = lane >> 2, tig = lane & 3;

    float acc[2][8][4];
#pragma unroll
    for (int i = 0; i < 2; i++)
#pragma unroll
        for (int j = 0; j < 8; j++)
#pragma unroll
            for (int c = 0; c < 4; c++) acc[i][j][c] = 0.f;

    const bool av = (m0 + lrow) < M, wv = (n0 + lrow) < N;
    const float* Ar = A + (size_t)(m0 + lrow) * K + lk;
    const float* Wr = W + (size_t)(n0 + lrow) * K + lk;
    float fA[8], fB[8];
    ld8(Ar, av, fA);
    ld8(Wr, wv, fB);
    storeA<8>(sA[0], oct, lrow, fA);
    storeB<132>(sB[0], oct, lrow, fB);
    __syncthreads();

    const int nk = K / 16;
    for (int kt = 0; kt < nk; kt++) {
        const int cur = kt & 1;
        const bool more = (kt + 1) < nk;
        if (more) {
            ld8(Ar + (kt + 1) * 16, av, fA);
            ld8(Wr + (kt + 1) * 16, wv, fB);
        }
#pragma unroll
        for (int o = 0; o < 2; o++) {
            uint4 a0 = loadA<8>(sA[cur], o, rb0, gid, tig);
            uint4 a1 = loadA<8>(sA[cur], o, rb0 + 1, gid, tig);
#pragma unroll
            for (int nt = 0; nt < 8; nt++) {
                uint2 bv = loadB<132>(sB[cur], o, tig, nB + nt * 8 + gid);
                mma_p(acc[0][nt], a0, bv);
                mma_p(acc[1][nt], a1, bv);
            }
        }
        if (more) {
            storeA<8>(sA[cur ^ 1], oct, lrow, fA);
            storeB<132>(sB[cur ^ 1], oct, lrow, fB);
            __syncthreads();
        }
    }

#pragma unroll
    for (int mt = 0; mt < 2; mt++) {
        int r = m0 + (rb0 + mt) * 16 + gid;
#pragma unroll
        for (int nt = 0; nt < 8; nt++) {
            int c = n0 + nB + nt * 8 + 2 * tig;
            float b0v = bias ? bias[c] : 0.f;
            float b1v = bias ? bias[c + 1] : 0.f;
            if (r < M)
                *(float2*)(C + (size_t)r * N + c) =
                    make_float2(acc[mt][nt][0] + b0v, acc[mt][nt][1] + b1v);
            if (r + 8 < M)
                *(float2*)(C + (size_t)(r + 8) * N + c) =
                    make_float2(acc[mt][nt][2] + b0v, acc[mt][nt][3] + b1v);
        }
    }
}

__global__ __launch_bounds__(256, 2) void gemm_tc_nt(
    const float* __restrict__ A, const float* __restrict__ W,
    const float* __restrict__ bias, float* __restrict__ C, int M, int N, int K) {
    gemm_body(A, W, bias, C, M, N, K, blockIdx.y * 128, blockIdx.x * 128);
}

__global__ __launch_bounds__(256, 2) void gemm_qkvp(
    const float* __restrict__ A, const float* __restrict__ rpe,
    const float* __restrict__ Wq, const float* __restrict__ Wk, const float* __restrict__ Wv,
    const float* __restrict__ Wp,
    const float* __restrict__ bq, const float* __restrict__ bk, const float* __restrict__ bv,
    float* __restrict__ Cq, float* __restrict__ Ck, float* __restrict__ Cv,
    float* __restrict__ Cp) {
    const int sel = blockIdx.x >> 3;
    if (sel == 3) {
        if (blockIdx.y >= 16) return;
        gemm_body(rpe, Wp, nullptr, Cp, Lc, Dc, Dc, blockIdx.y * 128, (blockIdx.x & 7) * 128);
        return;
    }
    const float* W = (sel == 0) ? Wq : (sel == 1) ? Wk : Wv;
    const float* bias = (sel == 0) ? bq : (sel == 1) ? bk : bv;
    float* C = (sel == 0) ? Cq : (sel == 1) ? Ck : Cv;
    gemm_body(A, W, bias, C, Bc * Tc, Dc, Dc, blockIdx.y * 128, (blockIdx.x & 7) * 128);
}

// ============================================================
// FUSED attention per (bh, 32-row q tile) — 512 threads (16 warps)
// for latency hiding; double-buffered strips, FMA exp.
// smem (u32): Sb 32*1028 | Au 8*264 | Av 8*264 | Bf 2*4608 | mx 32 | inv 32
// ============================================================
#define SB_STR 1028
#define AU_OFF (32 * SB_STR)
#define AV_OFF (AU_OFF + 8 * 264)
#define BF_OFF (AV_OFF + 8 * 264)
#define BF_STR 4608
#define MX_OFF (BF_OFF + 2 * BF_STR)
#define INV_OFF (MX_OFF + 32)
#define FUSED_SMEM_BYTES ((INV_OFF + 32) * 4)

__global__ __launch_bounds__(512, 1) void fused_attn(
    const float* __restrict__ Q, const float* __restrict__ K,
    const float* __restrict__ P, const float* __restrict__ V,
    const float* __restrict__ u, const float* __restrict__ vb,
    float* __restrict__ probs, float* __restrict__ ctx) {
    extern __shared__ __align__(16) uint32_t su[];
    float* Sb = (float*)su;
    uint32_t* Au = su + AU_OFF;
    uint32_t* Av = su + AV_OFF;
    uint32_t* Bf = su + BF_OFF;
    float* mx_s = (float*)(su + MX_OFF);
    float* inv_s = (float*)(su + INV_OFF);

    const int t = threadIdx.x;
    const int bh = blockIdx.y, zb = bh >> 4, h = bh & 15;
    const int q0 = blockIdx.x * 32;
    const int lane = t & 31, w = t >> 5;                  // 16 warps
    const int mB = (w & 1) * 16, rbw = w & 1, nBf = (w >> 1) * 8;
    const int gid = lane >> 2, tig = lane & 3;

    // ---- stage q+u (t<256) / q+v (t>=256) as packed A fragments ----
    {
        int tt = t & 255;
        int qr = tt >> 3, o = tt & 7;
        const float* qp = Q + ((size_t)(zb * Tc) + q0 + qr) * Dc + h * HSc + o * 8;
        float a[8], bb[8];
        ld8(qp, true, a);
        if (t < 256) {
            ld8(u + h * HSc + o * 8, true, bb);
#pragma unroll
            for (int i = 0; i < 8; i++) bb[i] += a[i];
            storeA<2>(Au, o, qr, bb);
        } else {
            ld8(vb + h * HSc + o * 8, true, bb);
#pragma unroll
            for (int i = 0; i < 8; i++) bb[i] += a[i];
            storeA<2>(Av, o, qr, bb);
        }
    }

    const int kr = t >> 3, oc8 = t & 7;   // staging: 64 rows x 8 octs
    float f0[8];
    uint4 aF[8];

    // ================= phase 1: ac = (q+u) K^T =================
    {
        const float* kp = K + ((size_t)(zb * Tc) + kr) * Dc + h * HSc + oc8 * 8;
        ld8(kp, true, f0);
        storeB<68>(Bf, oc8, kr, f0);
    }
    __syncthreads();
#pragma unroll
    for (int o = 0; o < 8; o++) aF[o] = loadA<2>(Au, o, rbw, gid, tig);
    {
        const float* kp = K + ((size_t)(zb * Tc) + 64 + kr) * Dc + h * HSc + oc8 * 8;
        ld8(kp, true, f0);
    }
    for (int s = 0; s < 16; s++) {
        const uint32_t* bufc = Bf + (s & 1) * BF_STR;
        if (s + 1 < 16) {
            uint32_t* bufn = Bf + ((s + 1) & 1) * BF_STR;
            storeB<68>(bufn, oc8, kr, f0);
            if (s + 2 < 16) {
                const float* kp =
                    K + ((size_t)(zb * Tc) + (s + 2) * 64 + kr) * Dc + h * HSc + oc8 * 8;
                ld8(kp, true, f0);
            }
        }
        float acc[4] = {0.f, 0.f, 0.f, 0.f};
#pragma unroll
        for (int o = 0; o < 8; o++)
            mma_p(acc, aF[o], loadB<68>(bufc, o, tig, nBf + gid));
        int col = s * 64 + nBf + 2 * tig;
        *(float2*)&Sb[(mB + gid) * SB_STR + col] = make_float2(acc[0], acc[1]);
        *(float2*)&Sb[(mB + gid + 8) * SB_STR + col] = make_float2(acc[2], acc[3]);
        __syncthreads();
    }

    // ================= phase 2: bd band, scatter-add =================
    const int lStart = (Tc - 1) - (q0 + 31);
#pragma unroll
    for (int o = 0; o < 8; o++) aF[o] = loadA<2>(Av, o, rbw, gid, tig);
    {
        int l = lStart + kr;
        if (l < Lc) ld8(P + (size_t)l * Dc + h * HSc + oc8 * 8, true, f0);
        else {
#pragma unroll
            for (int i = 0; i < 8; i++) f0[i] = 0.f;
        }
        storeB<68>(Bf, oc8, kr, f0);
    }
    __syncthreads();
    {
        int l = lStart + 64 + kr;
        if (l < Lc) ld8(P + (size_t)l * Dc + h * HSc + oc8 * 8, true, f0);
        else {
#pragma unroll
            for (int i = 0; i < 8; i++) f0[i] = 0.f;
        }
    }
    for (int s = 0; s < 17; s++) {
        int lBase = lStart + s * 64;
        const uint32_t* bufc = Bf + (s & 1) * BF_STR;
        if (s + 1 < 17) {
            uint32_t* bufn = Bf + ((s + 1) & 1) * BF_STR;
            storeB<68>(bufn, oc8, kr, f0);
            if (s + 2 < 17) {
                int l = lStart + (s + 2) * 64 + kr;
                if (l < Lc) ld8(P + (size_t)l * Dc + h * HSc + oc8 * 8, true, f0);
                else {
#pragma unroll
                    for (int i = 0; i < 8; i++) f0[i] = 0.f;
                }
            }
        }
        float acc[4] = {0.f, 0.f, 0.f, 0.f};
#pragma unroll
        for (int o = 0; o < 8; o++)
            mma_p(acc, aF[o], loadB<68>(bufc, o, tig, nBf + gid));
        int lc = lBase + nBf + 2 * tig;
        int m = mB + gid;
        int j = (q0 + m) + lc - (Tc - 1);
        if (j >= 0 && j < Tc) Sb[m * SB_STR + j] += acc[0];
        if (j + 1 >= 0 && j + 1 < Tc) Sb[m * SB_STR + j + 1] += acc[1];
        int j2 = j + 8;
        if (j2 >= 0 && j2 < Tc) Sb[(m + 8) * SB_STR + j2] += acc[2];
        if (j2 + 1 >= 0 && j2 + 1 < Tc) Sb[(m + 8) * SB_STR + j2 + 1] += acc[3];
        __syncthreads();
    }

    // ===== phase 3a: row max (2 rows/warp) =====
#pragma unroll
    for (int rr = 0; rr < 2; rr++) {
        int row_i = w * 2 + rr;
        const float* row = Sb + row_i * SB_STR;
        float mx = -3.4e38f;
        for (int c = lane; c < Tc; c += 32) mx = fmaxf(mx, row[c]);
#pragma unroll
        for (int o = 16; o; o >>= 1) mx = fmaxf(mx, __shfl_xor_sync(0xffffffffu, mx, o));
        if (lane == 0) mx_s[row_i] = mx;
    }
    __syncthreads();

    // ===== phase 4: exp (FMA) + ctx, double-buffered V =====
    const int row_e = t >> 4;           // 0..31
    const int ce = (t & 15) * 4;        // 4 floats per thread per strip
    const float mxc = mx_s[row_e] * EXP_SCALE;
    float psum = 0.f;
    float* erow = Sb + row_e * SB_STR;

    {   // exp strip 0
        float4 x0 = *(float4*)&erow[ce];
        x0.x = fexp2(fmaf(x0.x, EXP_SCALE, -mxc)); x0.y = fexp2(fmaf(x0.y, EXP_SCALE, -mxc));
        x0.z = fexp2(fmaf(x0.z, EXP_SCALE, -mxc)); x0.w = fexp2(fmaf(x0.w, EXP_SCALE, -mxc));
        *(float4*)&erow[ce] = x0;
        psum += x0.x + x0.y + x0.z + x0.w;
    }

    float acc2[4] = {0.f, 0.f, 0.f, 0.f};
    float fv[8];
    {
        const float* vp = V + ((size_t)(zb * Tc) + kr) * Dc + h * HSc + oc8 * 8;
        ld8(vp, true, fv);
        uint32_t* dst = Bf + kr * 72 + oc8 * 8;
        *(uint4*)(dst + 0) = make_uint4(tf32_of(fv[0]), tf32_of(fv[1]), tf32_of(fv[2]), tf32_of(fv[3]));
        *(uint4*)(dst + 4) = make_uint4(tf32_of(fv[4]), tf32_of(fv[5]), tf32_of(fv[6]), tf32_of(fv[7]));
    }
    __syncthreads();
    {
        const float* vp = V + ((size_t)(zb * Tc) + 64 + kr) * Dc + h * HSc + oc8 * 8;
        ld8(vp, true, fv);
    }
    for (int s = 0; s < 16; s++) {
        const uint32_t* Vtc = Bf + (s & 1) * BF_STR;
        if (s + 1 < 16) {
            uint32_t* Vtn = Bf + ((s + 1) & 1) * BF_STR;
            uint32_t* dst = Vtn + kr * 72 + oc8 * 8;
            *(uint4*)(dst + 0) = make_uint4(tf32_of(fv[0]), tf32_of(fv[1]), tf32_of(fv[2]), tf32_of(fv[3]));
            *(uint4*)(dst + 4) = make_uint4(tf32_of(fv[4]), tf32_of(fv[5]), tf32_of(fv[6]), tf32_of(fv[7]));
            if (s + 2 < 16) {
                const float* vp =
                    V + ((size_t)(zb * Tc) + (s + 2) * 64 + kr) * Dc + h * HSc + oc8 * 8;
                ld8(vp, true, fv);
            }
            float* ep = erow + (s + 1) * 64 + ce;
            float4 x0 = *(float4*)ep;
            x0.x = fexp2(fmaf(x0.x, EXP_SCALE, -mxc)); x0.y = fexp2(fmaf(x0.y, EXP_SCALE, -mxc));
            x0.z = fexp2(fmaf(x0.z, EXP_SCALE, -mxc)); x0.w = fexp2(fmaf(x0.w, EXP_SCALE, -mxc));
            *(float4*)ep = x0;
            psum += x0.x + x0.y + x0.z + x0.w;
        }

        const float* ar0 = Sb + (mB + gid) * SB_STR + s * 64;
        const float* ar8 = ar0 + 8 * SB_STR;
#pragma unroll
        for (int o = 0; o < 8; o++) {
            uint4 a;
            a.x = tf32_of(ar0[o * 8 + tig]);
            a.y = tf32_of(ar8[o * 8 + tig]);
            a.z = tf32_of(ar0[o * 8 + tig + 4]);
            a.w = tf32_of(ar8[o * 8 + tig + 4]);
            int c = nBf + gid;
            uint2 b;
            b.x = Vtc[(o * 8 + tig) * 72 + c];
            b.y = Vtc[(o * 8 + tig + 4) * 72 + c];
            mma_p(acc2, a, b);
        }
        __syncthreads();
    }

    // ---- row-sum reduce over 16 lanes sharing a row ----
#pragma unroll
    for (int o = 8; o; o >>= 1) psum += __shfl_xor_sync(0xffffffffu, psum, o);
    if ((lane & 15) == 0) inv_s[row_e] = 1.f / psum;
    __syncthreads();

    // ---- write probs = e * inv ----
    {
        float* pb = probs + ((size_t)bh << 20) + (size_t)q0 * Tc;
#pragma unroll 4
        for (int it = 0; it < 16; it++) {
            int idx = it * 512 + t;
            int r = idx >> 8, c4 = (idx & 255) * 4;
            float iv = inv_s[r];
            float4 val = *(float4*)&Sb[r * SB_STR + c4];
            val.x *= iv; val.y *= iv; val.z *= iv; val.w *= iv;
            *(float4*)(pb + (size_t)r * Tc + c4) = val;
        }
    }

    // ---- ctx epilogue: scale by inv ----
    {
        int r = q0 + mB + gid;
        float iv0 = inv_s[mB + gid], iv8 = inv_s[mB + gid + 8];
        int c = nBf + 2 * tig;
        *(float2*)(ctx + ((size_t)(zb * Tc) + r) * Dc + h * HSc + c) =
            make_float2(acc2[0] * iv0, acc2[1] * iv0);
        *(float2*)(ctx + ((size_t)(zb * Tc) + r + 8) * Dc + h * HSc + c) =
            make_float2(acc2[2] * iv8, acc2[3] * iv8);
    }
}

// ============================================================
extern "C" void kernel_launch(void* const* d_in, const int* in_sizes, int n_in,
                              void* d_out, int out_size) {
    const float* hs  = (const float*)d_in[0];
    const float* rpe = (const float*)d_in[1];
    const float* Wq  = (const float*)d_in[2];
    const float* bq  = (const float*)d_in[3];
    const float* Wk  = (const float*)d_in[4];
    const float* bk  = (const float*)d_in[5];
    const float* Wv  = (const float*)d_in[6];
    const float* bv  = (const float*)d_in[7];
    const float* Wo  = (const float*)d_in[8];
    const float* bo  = (const float*)d_in[9];
    const float* Wp  = (const float*)d_in[10];
    const float* pu  = (const float*)d_in[11];
    const float* pvb = (const float*)d_in[12];

    float* out = (float*)d_out;
    float* S   = out + (size_t)Bc * Tc * Dc;

    float *pq, *pk, *pv, *pp, *pctx;
    cudaGetSymbolAddress((void**)&pq,   g_q);
    cudaGetSymbolAddress((void**)&pk,   g_k);
    cudaGetSymbolAddress((void**)&pv,   g_v);
    cudaGetSymbolAddress((void**)&pp,   g_p);
    cudaGetSymbolAddress((void**)&pctx, g_ctx);

    cudaFuncSetAttribute(fused_attn, cudaFuncAttributeMaxDynamicSharedMemorySize,
                         FUSED_SMEM_BYTES);

    gemm_qkvp<<<dim3(32, 32), 256>>>(hs, rpe, Wq, Wk, Wv, Wp, bq, bk, bv,
                                     pq, pk, pv, pp);

    fused_attn<<<dim3(Tc / 32, Bc * Hc), 512, FUSED_SMEM_BYTES>>>(
        pq, pk, pp, pv, pu, pvb, S, pctx);

    gemm_tc_nt<<<dim3(8, 32), 256>>>(pctx, Wo, bo, out, Bc * Tc, Dc, Dc);
}